// round 1
// baseline (speedup 1.0000x reference)
#include <cuda_runtime.h>

// GASLayer: per-column EMA normalization scan over T timesteps.
// Exact chunked linear-recurrence scan (3 kernels), no approximation.

#define TT 32768
#define DD 1024
#define LL 256
#define CC (TT / LL)   // 128 chunks

#define ETA_MU  0.01f
#define ETA_VAR 0.02f
#define A_MU (1.0f - ETA_MU)   // 0.99
#define C_V  (1.0f - ETA_VAR)  // 0.98

// Scratch: chunk-boundary partials (device globals, no allocation).
__device__ float g_sum[CC][DD];
__device__ float g_sq [CC][DD];
__device__ float g_b  [CC][DD];   // zero-init mu scan value at chunk end
__device__ float g_p0 [CC][DD];   // sum c^{L-1-t} * eta_v * e_t^2
__device__ float g_p1 [CC][DD];   // sum c^{L-1-t} * eta_v * a^{t+1} * e_t
__device__ float g_ms [CC][DD];   // exact mu at chunk entry
__device__ float g_vs [CC][DD];   // exact var-slot at chunk entry

// Pass 1: chunk-local partials. One thread per column, L rows sequential.
__global__ __launch_bounds__(128) void gas_k1(const float* __restrict__ x) {
    const int col = blockIdx.y * 128 + threadIdx.x;
    const int c   = blockIdx.x;
    const float* xp = x + (size_t)c * LL * DD + col;

    float s = 0.f, s2 = 0.f, b = 0.f, p0 = 0.f, p1 = 0.f, w = 1.f;

    for (int t = 0; t < LL; t += 8) {
        float xb[8];
        #pragma unroll
        for (int u = 0; u < 8; u++) xb[u] = xp[(size_t)(t + u) * DD];
        #pragma unroll
        for (int u = 0; u < 8; u++) {
            float xv = xb[u];
            s  += xv;
            s2  = fmaf(xv, xv, s2);
            b   = fmaf(ETA_MU, xv - b, b);   // b = (1-eta)b + eta*x
            w  *= A_MU;                       // w = a^{t+1}
            float e = xv - b;
            p0 = fmaf(ETA_VAR * e, e, C_V * p0);
            p1 = fmaf(ETA_VAR * w, e, C_V * p1);
        }
    }
    g_sum[c][col] = s;  g_sq[c][col] = s2;  g_b[c][col] = b;
    g_p0[c][col] = p0;  g_p1[c][col] = p1;
}

// Pass 2: mu0/std0 + exact chunk-entry state chain (C steps per column).
__global__ __launch_bounds__(128) void gas_k2() {
    const int d = blockIdx.x * 128 + threadIdx.x;

    float s = 0.f, s2 = 0.f;
    for (int c = 0; c < CC; c++) { s += g_sum[c][d]; s2 += g_sq[c][d]; }
    float mu0  = s * (1.0f / TT);
    float varu = (s2 - (float)TT * mu0 * mu0) * (1.0f / (TT - 1));
    float std0 = sqrtf(fmaxf(varu, 0.f));   // torch.std (unbiased), stored in var slot

    // P2 = sum_t c^{L-1-t} * eta_v * a^{2(t+1)}  (universal constant), plus a^L, c^L.
    float p2 = 0.f, w = 1.f, cL = 1.f;
    for (int t = 0; t < LL; t++) {
        w  *= A_MU;
        p2  = fmaf(ETA_VAR * w, w, C_V * p2);
        cL *= C_V;
    }
    const float aL = w;

    float ms = mu0, vs = std0;
    for (int c = 0; c < CC; c++) {
        g_ms[c][d] = ms;
        g_vs[c][d] = vs;
        float bv = g_p0[c][d] - 2.f * ms * g_p1[c][d] + ms * ms * p2;
        vs = cL * vs + bv;
        ms = aL * ms + g_b[c][d];
    }
}

// Pass 3: true recurrence from exact entry state; emit all outputs.
__global__ __launch_bounds__(128) void gas_k3(const float* __restrict__ x,
                                              float* __restrict__ out) {
    const int col = blockIdx.y * 128 + threadIdx.x;
    const int c   = blockIdx.x;

    float m = g_ms[c][col];
    float v = g_vs[c][col];

    const float* xp   = x   + (size_t)c * LL * DD + col;
    float*       norm = out + (size_t)c * LL * DD + col;
    float*       info = out + (size_t)TT * DD + (size_t)c * LL * 2 * DD + col;

    for (int t = 0; t < LL; t += 8) {
        float xb[8];
        #pragma unroll
        for (int u = 0; u < 8; u++) xb[u] = xp[(size_t)(t + u) * DD];
        #pragma unroll
        for (int u = 0; u < 8; u++) {
            float xv = xb[u];
            m = fmaf(ETA_MU, xv - m, m);          // mu update (new mu used below)
            float r = xv - m;
            v = fmaf(ETA_VAR * r, r, C_V * v);    // var update
            norm[(size_t)(t + u) * DD]          = r * rsqrtf(v);
            info[(size_t)(t + u) * 2 * DD]      = m;
            info[(size_t)(t + u) * 2 * DD + DD] = v;
        }
    }
}

extern "C" void kernel_launch(void* const* d_in, const int* in_sizes, int n_in,
                              void* d_out, int out_size) {
    const float* x = (const float*)d_in[0];
    float* out = (float*)d_out;

    dim3 grid(CC, DD / 128);
    gas_k1<<<grid, 128>>>(x);
    gas_k2<<<DD / 128, 128>>>();
    gas_k3<<<grid, 128>>>(x, out);
}